// round 16
// baseline (speedup 1.0000x reference)
#include <cuda_runtime.h>

#define NN 50000
#define NE 200000
#define ET 250000   // edges + self loops
#define IC 14
#define HD 128
#define NH 8
#define OD 4
#define NS 0.2f
#define NB 196      // per-node blocks = ceil(NN/256)
#define HB 489      // hist blocks  = ceil(ET/512)
#define PSM 148     // SMs (B200)

typedef unsigned long long ull;

// ---- scratch (static __device__ arrays; zero-initialized at load) ----
__device__ int    g_deg[NN];            // self-cleaned each run
__device__ int    g_rowptr[NN + 1];
__device__ int    g_cursor[NN];
__device__ int    g_col[ET];
__device__ int    g_bsum[NB];
__device__ int    g_boff[256];
__device__ int    g_tick;               // epoch tickets: monotonic, never reset
__device__ int    g_ta;
__device__ int    g_tb;
__device__ int    g_tc;
__device__ int    g_td;
__device__ float  g_vs[IC * NH];
__device__ float  g_vd[IC * NH];
__device__ float4 g_as4[2 * NN];        // [half][n]: att-src heads 4h..4h+3
__device__ float4 g_ad4[2 * NN];
__device__ float4 g_x16[NN * 4];        // x rows padded 14 -> 16 floats
__device__ float  g_zT[NH * IC * NN];   // [h*IC+c][n]
__device__ float4 g_h2p[NH * NN];       // h2 partials per head
__device__ float4 g_h2[NN];             // combined h2
__device__ float  g_a2s[NN];
__device__ float  g_a2d[NN];
__device__ int    g_is64 = 1;

// ---- packed f32x2 helpers ----
__device__ __forceinline__ ull pk2(float lo, float hi) {
    ull r;
    asm("mov.b64 %0, {%1, %2};" : "=l"(r) : "f"(lo), "f"(hi));
    return r;
}
__device__ __forceinline__ void upk2(ull v, float& lo, float& hi) {
    asm("mov.b64 {%0, %1}, %2;" : "=f"(lo), "=f"(hi) : "l"(v));
}
__device__ __forceinline__ ull fma2(ull a, ull b, ull c) {
    ull d;
    asm("fma.rn.f32x2 %0, %1, %2, %3;" : "=l"(d) : "l"(a), "l"(b), "l"(c));
    return d;
}
__device__ __forceinline__ ull add2(ull a, ull b) {
    ull d;
    asm("add.rn.f32x2 %0, %1, %2;" : "=l"(d) : "l"(a), "l"(b));
    return d;
}
__device__ __forceinline__ ull mul2(ull a, ull b) {
    ull d;
    asm("mul.rn.f32x2 %0, %1, %2;" : "=l"(d) : "l"(a), "l"(b));
    return d;
}
__device__ __forceinline__ float lrelu(float v) {
    return (v >= 0.f) ? v : NS * v;
}
__device__ __forceinline__ float elu(float v) {
    return (v > 0.f) ? v : (__expf(v) - 1.f);
}

// all-resident grid barrier; epoch trick (monotonic counter, graph-replay safe)
__device__ __forceinline__ void grid_bar(int* cnt, int nb) {
    __threadfence();
    __syncthreads();
    if (threadIdx.x == 0) {
        int my = atomicAdd(cnt, 1);
        int target = (my / nb + 1) * nb;
        while (*((volatile int*)cnt) < target) {
            __nanosleep(64);
        }
    }
    __syncthreads();
    __threadfence();
}

__device__ __forceinline__ int load_edge(const void* ei, int idx, int is64) {
    if (is64) return (int)((const long long*)ei)[idx];
    return ((const int*)ei)[idx];
}

// Fused: dtype detect + (block 0) v_s/v_d precompute | grid barrier | histogram.
__global__ void __launch_bounds__(256, 8)
k_histF(const void* __restrict__ ei, const float* __restrict__ W1,
        const float* __restrict__ as1, const float* __restrict__ ad1) {
    __shared__ float sv[224], sd[224];
    const int t = threadIdx.x;
    const int bx = blockIdx.x;
    const int base = bx * 256 + t;
    const int* p = (const int*)ei;
#pragma unroll
    for (int k = 0; k < 2; k++) {
        int i = base + k * (HB * 256);
        if (i < NE && p[2 * i + 1] != 0) g_is64 = 0;
    }
    if (bx == 0) {
        if (t < 224) {
            int pp = t >> 1, part = t & 1;
            int c = pp / NH, h = pp % NH;
            float s = 0.f, d = 0.f;
            for (int f = part * 64; f < part * 64 + 64; f++) {
                float w = W1[c * (NH * HD) + h * HD + f];
                s = fmaf(w, as1[h * HD + f], s);
                d = fmaf(w, ad1[h * HD + f], d);
            }
            sv[t] = s;
            sd[t] = d;
        }
        __syncthreads();
        if (t < 112) {
            g_vs[t] = sv[2 * t] + sv[2 * t + 1];
            g_vd[t] = sd[2 * t] + sd[2 * t + 1];
        }
    }
    grid_bar(&g_ta, HB);
    const int is64 = g_is64;
#pragma unroll
    for (int k = 0; k < 2; k++) {
        int i = base + k * (HB * 256);
        if (i < ET) {
            int dst = (i < NE) ? load_edge(ei, NE + i, is64) : (i - NE);
            atomicAdd(&g_deg[dst], 1);
        }
    }
}

__device__ __forceinline__ int block_scan_256(int v, int t) {
    __shared__ int wt[8];
    int lane = t & 31, w = t >> 5;
    int s = v;
#pragma unroll
    for (int o = 1; o < 32; o <<= 1) {
        int u = __shfl_up_sync(0xffffffffu, s, o);
        if (lane >= o) s += u;
    }
    if (lane == 31) wt[w] = s;
    __syncthreads();
    if (t < 8) {
        int u = wt[t];
#pragma unroll
        for (int o = 1; o < 8; o <<= 1) {
            int x = __shfl_up_sync(0xffu, u, o);
            if (t >= o) u += x;
        }
        wt[t] = u;
    }
    __syncthreads();
    return s + (w > 0 ? wt[w - 1] : 0);  // inclusive
}

// Fused CSR build: scan | bar | fixup + alpha scalars + padded x | bar | scatter.
__global__ void __launch_bounds__(256)
k_build(const float* __restrict__ x, const void* __restrict__ ei) {
    __shared__ float vs[IC * NH], vd[IC * NH];
    __shared__ int lastsh;
    const int t = threadIdx.x;
    const int bx = blockIdx.x;
    if (t < IC * NH) {
        vs[t] = g_vs[t];
        vd[t] = g_vd[t];
    }
    // ---- phase A: scan ----
    int i = bx * 256 + t;
    int v = 0;
    if (i < NN) {
        v = g_deg[i];
        g_deg[i] = 0;  // self-clean for next replay
    }
    int incl = block_scan_256(v, t);
    if (i < NN) g_rowptr[i] = incl - v;
    if (t == 255) g_bsum[bx] = incl;
    __threadfence();
    __syncthreads();
    if (t == 0) lastsh = ((atomicAdd(&g_tick, 1) % NB) == NB - 1);
    __syncthreads();
    if (lastsh) {
        __threadfence();
        int u = (t < NB) ? *((volatile int*)&g_bsum[t]) : 0;
        int incl2 = block_scan_256(u, t);
        if (t < NB) g_boff[t] = incl2 - u;
        if (t == NB - 1) g_rowptr[NN] = incl2;
    }
    grid_bar(&g_tb, NB);
    // ---- phase B: fixup + alpha + x16 ----
    const int n = i;
    if (n < NN) {
        int r = g_rowptr[n] + g_boff[bx];
        g_rowptr[n] = r;
        g_cursor[n] = r;
        float xr[IC];
#pragma unroll
        for (int c = 0; c < IC; c++) xr[c] = x[n * IC + c];
        float4 xv;
        xv.x = xr[0]; xv.y = xr[1]; xv.z = xr[2]; xv.w = xr[3];
        g_x16[4 * n + 0] = xv;
        xv.x = xr[4]; xv.y = xr[5]; xv.z = xr[6]; xv.w = xr[7];
        g_x16[4 * n + 1] = xv;
        xv.x = xr[8]; xv.y = xr[9]; xv.z = xr[10]; xv.w = xr[11];
        g_x16[4 * n + 2] = xv;
        xv.x = xr[12]; xv.y = xr[13]; xv.z = 0.f; xv.w = 0.f;
        g_x16[4 * n + 3] = xv;
        float a[NH], d[NH];
#pragma unroll
        for (int h = 0; h < NH; h++) {
            float s = 0.f, dd = 0.f;
#pragma unroll
            for (int c = 0; c < IC; c++) {
                s = fmaf(xr[c], vs[c * NH + h], s);
                dd = fmaf(xr[c], vd[c * NH + h], dd);
            }
            a[h] = s;
            d[h] = dd;
        }
        g_as4[n] = make_float4(a[0], a[1], a[2], a[3]);
        g_as4[NN + n] = make_float4(a[4], a[5], a[6], a[7]);
        g_ad4[n] = make_float4(d[0], d[1], d[2], d[3]);
        g_ad4[NN + n] = make_float4(d[4], d[5], d[6], d[7]);
    }
    grid_bar(&g_tc, NB);
    // ---- phase C: scatter ----
    const int is64 = g_is64;
    const int stride = NB * 256;
    for (int e = bx * 256 + t; e < ET; e += stride) {
        int src, dst;
        if (e < NE) {
            src = load_edge(ei, e, is64);
            dst = load_edge(ei, NE + e, is64);
        } else {
            src = e - NE;
            dst = e - NE;
        }
        int pos = atomicAdd(&g_cursor[dst], 1);
        g_col[pos] = src;
    }
}

// Aggregation: ONE thread per node, ALL 8 heads, single edge pass.
__global__ void __launch_bounds__(128, 2) k_agg() {
    int n = blockIdx.x * 128 + threadIdx.x;
    if (n >= NN) return;
    const float4 d0 = g_ad4[n], d1 = g_ad4[NN + n];
    const int r0 = g_rowptr[n], r1 = g_rowptr[n + 1];
    ull zc[NH][7];
#pragma unroll
    for (int h = 0; h < NH; h++)
#pragma unroll
        for (int cp = 0; cp < 7; cp++) zc[h][cp] = 0;
    float ss[NH];
#pragma unroll
    for (int h = 0; h < NH; h++) ss[h] = 0.f;
    for (int e = r0; e < r1; e++) {
        int s = g_col[e];
        float4 a0 = g_as4[s], a1 = g_as4[NN + s];
        float w[NH];
        w[0] = __expf(lrelu(a0.x + d0.x));
        w[1] = __expf(lrelu(a0.y + d0.y));
        w[2] = __expf(lrelu(a0.z + d0.z));
        w[3] = __expf(lrelu(a0.w + d0.w));
        w[4] = __expf(lrelu(a1.x + d1.x));
        w[5] = __expf(lrelu(a1.y + d1.y));
        w[6] = __expf(lrelu(a1.z + d1.z));
        w[7] = __expf(lrelu(a1.w + d1.w));
        const ull* xp = (const ull*)&g_x16[4 * s];
        ull xx[7];
#pragma unroll
        for (int cp = 0; cp < 7; cp++) xx[cp] = xp[cp];
#pragma unroll
        for (int h = 0; h < NH; h++) {
            ss[h] += w[h];
            ull wh = pk2(w[h], w[h]);
#pragma unroll
            for (int cp = 0; cp < 7; cp++)
                zc[h][cp] = fma2(wh, xx[cp], zc[h][cp]);
        }
    }
#pragma unroll
    for (int h = 0; h < NH; h++) {
        float inv = 1.f / (ss[h] + 1e-16f);
        ull iv = pk2(inv, inv);
#pragma unroll
        for (int cp = 0; cp < 7; cp++) {
            float lo, hi;
            upk2(mul2(zc[h][cp], iv), lo, hi);
            g_zT[(h * IC + 2 * cp) * NN + n] = lo;
            g_zT[(h * IC + 2 * cp + 1) * NN + n] = hi;
        }
    }
}

// Per-node inner body for the projection (one 64-row weight tile pass).
__device__ __forceinline__ void proj_node(const ull* __restrict__ zz,
                                          const ull (*sw)[20],
                                          ull& h2a, ull& h2b) {
#pragma unroll 2
    for (int q = 0; q < 64; q++) {
        const ulonglong2* row = (const ulonglong2*)&sw[q][0];
        ulonglong2 w0 = row[0], w1 = row[1], w2 = row[2], w3 = row[3];
        ulonglong2 w4 = row[4], w5 = row[5], w6 = row[6];
        ull a0 = sw[q][14], a1 = 0;
        a0 = fma2(zz[0], w0.x, a0);  a1 = fma2(zz[1], w0.y, a1);
        a0 = fma2(zz[2], w1.x, a0);  a1 = fma2(zz[3], w1.y, a1);
        a0 = fma2(zz[4], w2.x, a0);  a1 = fma2(zz[5], w2.y, a1);
        a0 = fma2(zz[6], w3.x, a0);  a1 = fma2(zz[7], w3.y, a1);
        a0 = fma2(zz[8], w4.x, a0);  a1 = fma2(zz[9], w4.y, a1);
        a0 = fma2(zz[10], w5.x, a0); a1 = fma2(zz[11], w5.y, a1);
        a0 = fma2(zz[12], w6.x, a0); a1 = fma2(zz[13], w6.y, a1);
        a0 = add2(a0, a1);
        float t0, t1;
        upk2(a0, t0, t1);
        float e0 = elu(t0);
        float e1 = elu(t1);
        ull aa0 = pk2(e0, e0), aa1 = pk2(e1, e1);
        const ulonglong2 w2a = *(const ulonglong2*)&sw[q][16];
        const ulonglong2 w2b = *(const ulonglong2*)&sw[q][18];
        h2a = fma2(aa0, w2a.x, h2a);
        h2b = fma2(aa0, w2a.y, h2b);
        h2a = fma2(aa1, w2b.x, h2a);
        h2b = fma2(aa1, w2b.y, h2b);
    }
}

// Projection: PERSISTENT blocks, 2D grid (PSM, NH). blockIdx.y = head;
// block grid-strides over nodes (stride PSM*128). 10KB head tile loaded once.
// Outer loop pinned to unroll 1 (bounded ptxas work); inner unroll 2.
__global__ void __launch_bounds__(128, 8)
k_proj(const float* __restrict__ W1, const float* __restrict__ b1,
       const float* __restrict__ W2) {
    __shared__ ull sw[64][20];  // 10240 B
    const int t = threadIdx.x;
    const int head = blockIdx.y;
    if (t < 64) {
        int o0 = head * HD + 2 * t, o1 = o0 + 1;
#pragma unroll
        for (int c = 0; c < IC; c++)
            sw[t][c] = pk2(W1[c * (NH * HD) + o0], W1[c * (NH * HD) + o1]);
        sw[t][14] = pk2(b1[o0], b1[o1]);
        sw[t][15] = 0;
        sw[t][16] = pk2(W2[o0 * OD + 0], W2[o0 * OD + 1]);
        sw[t][17] = pk2(W2[o0 * OD + 2], W2[o0 * OD + 3]);
        sw[t][18] = pk2(W2[o1 * OD + 0], W2[o1 * OD + 1]);
        sw[t][19] = pk2(W2[o1 * OD + 2], W2[o1 * OD + 3]);
    }
    __syncthreads();

    const float* zbase = g_zT + head * IC * NN;
#pragma unroll 1
    for (int n = blockIdx.x * 128 + t; n < NN; n += PSM * 128) {
        ull zz[IC];
#pragma unroll
        for (int c = 0; c < IC; c++) {
            float zv = zbase[c * NN + n];
            zz[c] = pk2(zv, zv);
        }
        ull h2a = 0, h2b = 0;
        proj_node(zz, sw, h2a, h2b);
        float4 o4;
        upk2(h2a, o4.x, o4.y);
        upk2(h2b, o4.z, o4.w);
        g_h2p[head * NN + n] = o4;
    }
}

// Layer-2: phase A combines 8 head partials + precomputes a2 scalars
//          | grid barrier | phase B: softmax-aggregate.
__global__ void __launch_bounds__(256)
k_layer2(float* __restrict__ out, const float* __restrict__ b2,
         const float* __restrict__ as2, const float* __restrict__ ad2) {
    const int t = threadIdx.x;
    const int n = blockIdx.x * 256 + t;
    const float s0 = __ldg(as2 + 0), s1 = __ldg(as2 + 1),
                s2 = __ldg(as2 + 2), s3 = __ldg(as2 + 3);
    if (n < NN) {
        float hx = 0.f, hy = 0.f, hz = 0.f, hw = 0.f;
#pragma unroll
        for (int h = 0; h < NH; h++) {
            float4 p = g_h2p[h * NN + n];
            hx += p.x; hy += p.y; hz += p.z; hw += p.w;
        }
        g_h2[n] = make_float4(hx, hy, hz, hw);
        g_a2s[n] = hx * s0 + hy * s1 + hz * s2 + hw * s3;
        g_a2d[n] = hx * __ldg(ad2 + 0) + hy * __ldg(ad2 + 1) +
                   hz * __ldg(ad2 + 2) + hw * __ldg(ad2 + 3);
    }
    grid_bar(&g_td, NB);
    if (n >= NN) return;
    const float adn = g_a2d[n];
    const int r0 = g_rowptr[n], r1 = g_rowptr[n + 1];
    float ss = 0.f, ax = 0.f, ay = 0.f, az = 0.f, aw = 0.f;
    for (int e = r0; e < r1; e++) {
        int s = g_col[e];
        float v = lrelu(g_a2s[s] + adn);
        float w = __expf(v);
        ss += w;
        float4 hv = g_h2[s];
        ax = fmaf(w, hv.x, ax);
        ay = fmaf(w, hv.y, ay);
        az = fmaf(w, hv.z, az);
        aw = fmaf(w, hv.w, aw);
    }
    float inv = 1.f / (ss + 1e-16f);
    float4 o4;
    o4.x = ax * inv + __ldg(b2 + 0);
    o4.y = ay * inv + __ldg(b2 + 1);
    o4.z = az * inv + __ldg(b2 + 2);
    o4.w = aw * inv + __ldg(b2 + 3);
    ((float4*)out)[n] = o4;
}

extern "C" void kernel_launch(void* const* d_in, const int* in_sizes, int n_in,
                              void* d_out, int out_size) {
    const float* x   = (const float*)d_in[0];
    const void*  ei  = d_in[1];
    const float* W1  = (const float*)d_in[2];
    const float* as1 = (const float*)d_in[3];
    const float* ad1 = (const float*)d_in[4];
    const float* b1  = (const float*)d_in[5];
    const float* W2  = (const float*)d_in[6];
    const float* as2 = (const float*)d_in[7];
    const float* ad2 = (const float*)d_in[8];
    const float* b2  = (const float*)d_in[9];
    float* out = (float*)d_out;

    k_histF<<<HB, 256>>>(ei, W1, as1, ad1);
    k_build<<<NB, 256>>>(x, ei);
    k_agg<<<(NN + 127) / 128, 128>>>();
    dim3 pg(PSM, NH);
    k_proj<<<pg, 128>>>(W1, b1, W2);
    k_layer2<<<NB, 256>>>(out, b2, as2, ad2);
}

// round 17
// speedup vs baseline: 1.1207x; 1.1207x over previous
#include <cuda_runtime.h>

#define NN 50000
#define NE 200000
#define ET 250000   // edges + self loops
#define IC 14
#define HD 128
#define NH 8
#define OD 4
#define NS 0.2f
#define NB 196      // per-node blocks = ceil(NN/256)
#define HB 489      // hist blocks  = ceil(ET/512)

typedef unsigned long long ull;

// ---- scratch (static __device__ arrays; zero-initialized at load) ----
__device__ int    g_deg[NN];            // self-cleaned each run
__device__ int    g_rowptr[NN + 1];
__device__ int    g_cursor[NN];
__device__ int    g_col[ET];
__device__ int    g_bsum[NB];
__device__ int    g_boff[256];
__device__ int    g_tick;               // epoch tickets: monotonic, never reset
__device__ int    g_ta;
__device__ int    g_tb;
__device__ int    g_tc;
__device__ int    g_td;
__device__ float  g_vs[IC * NH];
__device__ float  g_vd[IC * NH];
__device__ float4 g_as4[2 * NN];        // [half][n]: att-src heads 4h..4h+3
__device__ float4 g_ad4[2 * NN];
__device__ float4 g_x16[NN * 4];        // x rows padded 14 -> 16 floats
__device__ float  g_zT[NH * IC * NN];   // [h*IC+c][n]
__device__ float4 g_h2p[NH * NN];       // h2 partials per head
__device__ float4 g_h2[NN];             // combined h2
__device__ float  g_a2s[NN];
__device__ float  g_a2d[NN];
__device__ int    g_is64 = 1;

// ---- packed f32x2 helpers ----
__device__ __forceinline__ ull pk2(float lo, float hi) {
    ull r;
    asm("mov.b64 %0, {%1, %2};" : "=l"(r) : "f"(lo), "f"(hi));
    return r;
}
__device__ __forceinline__ void upk2(ull v, float& lo, float& hi) {
    asm("mov.b64 {%0, %1}, %2;" : "=f"(lo), "=f"(hi) : "l"(v));
}
__device__ __forceinline__ ull fma2(ull a, ull b, ull c) {
    ull d;
    asm("fma.rn.f32x2 %0, %1, %2, %3;" : "=l"(d) : "l"(a), "l"(b), "l"(c));
    return d;
}
__device__ __forceinline__ ull add2(ull a, ull b) {
    ull d;
    asm("add.rn.f32x2 %0, %1, %2;" : "=l"(d) : "l"(a), "l"(b));
    return d;
}
__device__ __forceinline__ ull mul2(ull a, ull b) {
    ull d;
    asm("mul.rn.f32x2 %0, %1, %2;" : "=l"(d) : "l"(a), "l"(b));
    return d;
}
__device__ __forceinline__ float lrelu(float v) {
    return (v >= 0.f) ? v : NS * v;
}

// all-resident grid barrier; epoch trick (monotonic counter, graph-replay safe)
__device__ __forceinline__ void grid_bar(int* cnt, int nb) {
    __threadfence();
    __syncthreads();
    if (threadIdx.x == 0) {
        int my = atomicAdd(cnt, 1);
        int target = (my / nb + 1) * nb;
        while (*((volatile int*)cnt) < target) {
            __nanosleep(64);
        }
    }
    __syncthreads();
    __threadfence();
}

__device__ __forceinline__ int load_edge(const void* ei, int idx, int is64) {
    if (is64) return (int)((const long long*)ei)[idx];
    return ((const int*)ei)[idx];
}

// Fused: dtype detect + (block 0) v_s/v_d precompute | grid barrier | histogram.
__global__ void __launch_bounds__(256, 8)
k_histF(const void* __restrict__ ei, const float* __restrict__ W1,
        const float* __restrict__ as1, const float* __restrict__ ad1) {
    __shared__ float sv[224], sd[224];
    const int t = threadIdx.x;
    const int bx = blockIdx.x;
    const int base = bx * 256 + t;
    const int* p = (const int*)ei;
#pragma unroll
    for (int k = 0; k < 2; k++) {
        int i = base + k * (HB * 256);
        if (i < NE && p[2 * i + 1] != 0) g_is64 = 0;
    }
    if (bx == 0) {
        if (t < 224) {
            int pp = t >> 1, part = t & 1;
            int c = pp / NH, h = pp % NH;
            float s = 0.f, d = 0.f;
            for (int f = part * 64; f < part * 64 + 64; f++) {
                float w = W1[c * (NH * HD) + h * HD + f];
                s = fmaf(w, as1[h * HD + f], s);
                d = fmaf(w, ad1[h * HD + f], d);
            }
            sv[t] = s;
            sd[t] = d;
        }
        __syncthreads();
        if (t < 112) {
            g_vs[t] = sv[2 * t] + sv[2 * t + 1];
            g_vd[t] = sd[2 * t] + sd[2 * t + 1];
        }
    }
    grid_bar(&g_ta, HB);
    const int is64 = g_is64;
#pragma unroll
    for (int k = 0; k < 2; k++) {
        int i = base + k * (HB * 256);
        if (i < ET) {
            int dst = (i < NE) ? load_edge(ei, NE + i, is64) : (i - NE);
            atomicAdd(&g_deg[dst], 1);
        }
    }
}

__device__ __forceinline__ int block_scan_256(int v, int t) {
    __shared__ int wt[8];
    int lane = t & 31, w = t >> 5;
    int s = v;
#pragma unroll
    for (int o = 1; o < 32; o <<= 1) {
        int u = __shfl_up_sync(0xffffffffu, s, o);
        if (lane >= o) s += u;
    }
    if (lane == 31) wt[w] = s;
    __syncthreads();
    if (t < 8) {
        int u = wt[t];
#pragma unroll
        for (int o = 1; o < 8; o <<= 1) {
            int x = __shfl_up_sync(0xffu, u, o);
            if (t >= o) u += x;
        }
        wt[t] = u;
    }
    __syncthreads();
    return s + (w > 0 ? wt[w - 1] : 0);  // inclusive
}

// Fused CSR build: scan | bar | fixup + alpha scalars + padded x | bar | scatter.
__global__ void __launch_bounds__(256)
k_build(const float* __restrict__ x, const void* __restrict__ ei) {
    __shared__ float vs[IC * NH], vd[IC * NH];
    __shared__ int lastsh;
    const int t = threadIdx.x;
    const int bx = blockIdx.x;
    if (t < IC * NH) {
        vs[t] = g_vs[t];
        vd[t] = g_vd[t];
    }
    // ---- phase A: scan ----
    int i = bx * 256 + t;
    int v = 0;
    if (i < NN) {
        v = g_deg[i];
        g_deg[i] = 0;  // self-clean for next replay
    }
    int incl = block_scan_256(v, t);
    if (i < NN) g_rowptr[i] = incl - v;
    if (t == 255) g_bsum[bx] = incl;
    __threadfence();
    __syncthreads();
    if (t == 0) lastsh = ((atomicAdd(&g_tick, 1) % NB) == NB - 1);
    __syncthreads();
    if (lastsh) {
        __threadfence();
        int u = (t < NB) ? *((volatile int*)&g_bsum[t]) : 0;
        int incl2 = block_scan_256(u, t);
        if (t < NB) g_boff[t] = incl2 - u;
        if (t == NB - 1) g_rowptr[NN] = incl2;
    }
    grid_bar(&g_tb, NB);
    // ---- phase B: fixup + alpha + x16 ----
    const int n = i;
    if (n < NN) {
        int r = g_rowptr[n] + g_boff[bx];
        g_rowptr[n] = r;
        g_cursor[n] = r;
        float xr[IC];
#pragma unroll
        for (int c = 0; c < IC; c++) xr[c] = x[n * IC + c];
        float4 xv;
        xv.x = xr[0]; xv.y = xr[1]; xv.z = xr[2]; xv.w = xr[3];
        g_x16[4 * n + 0] = xv;
        xv.x = xr[4]; xv.y = xr[5]; xv.z = xr[6]; xv.w = xr[7];
        g_x16[4 * n + 1] = xv;
        xv.x = xr[8]; xv.y = xr[9]; xv.z = xr[10]; xv.w = xr[11];
        g_x16[4 * n + 2] = xv;
        xv.x = xr[12]; xv.y = xr[13]; xv.z = 0.f; xv.w = 0.f;
        g_x16[4 * n + 3] = xv;
        float a[NH], d[NH];
#pragma unroll
        for (int h = 0; h < NH; h++) {
            float s = 0.f, dd = 0.f;
#pragma unroll
            for (int c = 0; c < IC; c++) {
                s = fmaf(xr[c], vs[c * NH + h], s);
                dd = fmaf(xr[c], vd[c * NH + h], dd);
            }
            a[h] = s;
            d[h] = dd;
        }
        g_as4[n] = make_float4(a[0], a[1], a[2], a[3]);
        g_as4[NN + n] = make_float4(a[4], a[5], a[6], a[7]);
        g_ad4[n] = make_float4(d[0], d[1], d[2], d[3]);
        g_ad4[NN + n] = make_float4(d[4], d[5], d[6], d[7]);
    }
    grid_bar(&g_tc, NB);
    // ---- phase C: scatter ----
    const int is64 = g_is64;
    const int stride = NB * 256;
    for (int e = bx * 256 + t; e < ET; e += stride) {
        int src, dst;
        if (e < NE) {
            src = load_edge(ei, e, is64);
            dst = load_edge(ei, NE + e, is64);
        } else {
            src = e - NE;
            dst = e - NE;
        }
        int pos = atomicAdd(&g_cursor[dst], 1);
        g_col[pos] = src;
    }
}

// Aggregation: ONE thread per node, ALL 8 heads, 2 edges per iteration
// (2x memory-level parallelism on the col->as4/x16 pointer chase).
__global__ void __launch_bounds__(128, 2) k_agg() {
    int n = blockIdx.x * 128 + threadIdx.x;
    if (n >= NN) return;
    const float4 d0 = g_ad4[n], d1 = g_ad4[NN + n];
    const int r0 = g_rowptr[n], r1 = g_rowptr[n + 1];
    ull zc[NH][7];
#pragma unroll
    for (int h = 0; h < NH; h++)
#pragma unroll
        for (int cp = 0; cp < 7; cp++) zc[h][cp] = 0;
    float ss[NH];
#pragma unroll
    for (int h = 0; h < NH; h++) ss[h] = 0.f;
    int e = r0;
    for (; e + 1 < r1; e += 2) {
        int sa = g_col[e];
        int sb = g_col[e + 1];
        float4 a0a = g_as4[sa], a1a = g_as4[NN + sa];
        float4 a0b = g_as4[sb], a1b = g_as4[NN + sb];
        const ull* xpa = (const ull*)&g_x16[4 * sa];
        const ull* xpb = (const ull*)&g_x16[4 * sb];
        ull xxa[7], xxb[7];
#pragma unroll
        for (int cp = 0; cp < 7; cp++) { xxa[cp] = xpa[cp]; xxb[cp] = xpb[cp]; }
        float wa[NH], wb[NH];
        wa[0] = __expf(lrelu(a0a.x + d0.x));
        wa[1] = __expf(lrelu(a0a.y + d0.y));
        wa[2] = __expf(lrelu(a0a.z + d0.z));
        wa[3] = __expf(lrelu(a0a.w + d0.w));
        wa[4] = __expf(lrelu(a1a.x + d1.x));
        wa[5] = __expf(lrelu(a1a.y + d1.y));
        wa[6] = __expf(lrelu(a1a.z + d1.z));
        wa[7] = __expf(lrelu(a1a.w + d1.w));
        wb[0] = __expf(lrelu(a0b.x + d0.x));
        wb[1] = __expf(lrelu(a0b.y + d0.y));
        wb[2] = __expf(lrelu(a0b.z + d0.z));
        wb[3] = __expf(lrelu(a0b.w + d0.w));
        wb[4] = __expf(lrelu(a1b.x + d1.x));
        wb[5] = __expf(lrelu(a1b.y + d1.y));
        wb[6] = __expf(lrelu(a1b.z + d1.z));
        wb[7] = __expf(lrelu(a1b.w + d1.w));
#pragma unroll
        for (int h = 0; h < NH; h++) {
            ss[h] += wa[h] + wb[h];
            ull wha = pk2(wa[h], wa[h]);
            ull whb = pk2(wb[h], wb[h]);
#pragma unroll
            for (int cp = 0; cp < 7; cp++) {
                zc[h][cp] = fma2(wha, xxa[cp], zc[h][cp]);
                zc[h][cp] = fma2(whb, xxb[cp], zc[h][cp]);
            }
        }
    }
    if (e < r1) {
        int s = g_col[e];
        float4 a0 = g_as4[s], a1 = g_as4[NN + s];
        float w[NH];
        w[0] = __expf(lrelu(a0.x + d0.x));
        w[1] = __expf(lrelu(a0.y + d0.y));
        w[2] = __expf(lrelu(a0.z + d0.z));
        w[3] = __expf(lrelu(a0.w + d0.w));
        w[4] = __expf(lrelu(a1.x + d1.x));
        w[5] = __expf(lrelu(a1.y + d1.y));
        w[6] = __expf(lrelu(a1.z + d1.z));
        w[7] = __expf(lrelu(a1.w + d1.w));
        const ull* xp = (const ull*)&g_x16[4 * s];
        ull xx[7];
#pragma unroll
        for (int cp = 0; cp < 7; cp++) xx[cp] = xp[cp];
#pragma unroll
        for (int h = 0; h < NH; h++) {
            ss[h] += w[h];
            ull wh = pk2(w[h], w[h]);
#pragma unroll
            for (int cp = 0; cp < 7; cp++)
                zc[h][cp] = fma2(wh, xx[cp], zc[h][cp]);
        }
    }
#pragma unroll
    for (int h = 0; h < NH; h++) {
        float inv = 1.f / (ss[h] + 1e-16f);
        ull iv = pk2(inv, inv);
#pragma unroll
        for (int cp = 0; cp < 7; cp++) {
            float lo, hi;
            upk2(mul2(zc[h][cp], iv), lo, hi);
            g_zT[(h * IC + 2 * cp) * NN + n] = lo;
            g_zT[(h * IC + 2 * cp + 1) * NN + n] = hi;
        }
    }
}

// Projection: blockIdx.y = HEAD (10KB smem tile of 64 output-pairs), 128
// threads, 2 nodes per thread. Grid = 196*8 = 1568 blocks (R12 proven shape).
#define SW_ROW 20
__global__ void __launch_bounds__(128, 8)
k_proj(const float* __restrict__ W1, const float* __restrict__ b1,
       const float* __restrict__ W2) {
    __shared__ ull sw[64][SW_ROW];  // 10240 B
    const int t = threadIdx.x;
    const int head = blockIdx.y;
    if (t < 64) {
        int p = t;
        int o0 = head * HD + 2 * p, o1 = o0 + 1;
#pragma unroll
        for (int c = 0; c < IC; c++)
            sw[p][c] = pk2(W1[c * (NH * HD) + o0], W1[c * (NH * HD) + o1]);
        sw[p][14] = pk2(b1[o0], b1[o1]);
        sw[p][15] = 0;
        sw[p][16] = pk2(W2[o0 * OD + 0], W2[o0 * OD + 1]);
        sw[p][17] = pk2(W2[o0 * OD + 2], W2[o0 * OD + 3]);
        sw[p][18] = pk2(W2[o1 * OD + 0], W2[o1 * OD + 1]);
        sw[p][19] = pk2(W2[o1 * OD + 2], W2[o1 * OD + 3]);
    }
    __syncthreads();
    const int n0 = blockIdx.x * 256 + t;
    const int n1 = n0 + 128;
    const bool v1 = (n1 < NN);
    if (n0 >= NN) return;

    ull zzA[IC], zzB[IC];
#pragma unroll
    for (int c = 0; c < IC; c++) {
        float za = g_zT[(head * IC + c) * NN + n0];
        zzA[c] = pk2(za, za);
        float zb = v1 ? g_zT[(head * IC + c) * NN + n1] : 0.f;
        zzB[c] = pk2(zb, zb);
    }
    ull h2aA = 0, h2bA = 0, h2aB = 0, h2bB = 0;
#pragma unroll 4
    for (int q = 0; q < 64; q++) {
        const ulonglong2* row = (const ulonglong2*)&sw[q][0];
        ulonglong2 w0 = row[0], w1 = row[1], w2 = row[2], w3 = row[3];
        ulonglong2 w4 = row[4], w5 = row[5], w6 = row[6];
        const ull bb = sw[q][14];
        const ulonglong2 w2a = *(const ulonglong2*)&sw[q][16];
        const ulonglong2 w2b = *(const ulonglong2*)&sw[q][18];
        // node A
        {
            ull a0 = bb, a1 = 0;
            a0 = fma2(zzA[0], w0.x, a0);  a1 = fma2(zzA[1], w0.y, a1);
            a0 = fma2(zzA[2], w1.x, a0);  a1 = fma2(zzA[3], w1.y, a1);
            a0 = fma2(zzA[4], w2.x, a0);  a1 = fma2(zzA[5], w2.y, a1);
            a0 = fma2(zzA[6], w3.x, a0);  a1 = fma2(zzA[7], w3.y, a1);
            a0 = fma2(zzA[8], w4.x, a0);  a1 = fma2(zzA[9], w4.y, a1);
            a0 = fma2(zzA[10], w5.x, a0); a1 = fma2(zzA[11], w5.y, a1);
            a0 = fma2(zzA[12], w6.x, a0); a1 = fma2(zzA[13], w6.y, a1);
            a0 = add2(a0, a1);
            float t0, t1;
            upk2(a0, t0, t1);
            float e0 = (t0 > 0.f) ? t0 : (__expf(t0) - 1.f);
            float e1 = (t1 > 0.f) ? t1 : (__expf(t1) - 1.f);
            ull aa0 = pk2(e0, e0), aa1 = pk2(e1, e1);
            h2aA = fma2(aa0, w2a.x, h2aA);
            h2bA = fma2(aa0, w2a.y, h2bA);
            h2aA = fma2(aa1, w2b.x, h2aA);
            h2bA = fma2(aa1, w2b.y, h2bA);
        }
        // node B
        {
            ull a0 = bb, a1 = 0;
            a0 = fma2(zzB[0], w0.x, a0);  a1 = fma2(zzB[1], w0.y, a1);
            a0 = fma2(zzB[2], w1.x, a0);  a1 = fma2(zzB[3], w1.y, a1);
            a0 = fma2(zzB[4], w2.x, a0);  a1 = fma2(zzB[5], w2.y, a1);
            a0 = fma2(zzB[6], w3.x, a0);  a1 = fma2(zzB[7], w3.y, a1);
            a0 = fma2(zzB[8], w4.x, a0);  a1 = fma2(zzB[9], w4.y, a1);
            a0 = fma2(zzB[10], w5.x, a0); a1 = fma2(zzB[11], w5.y, a1);
            a0 = fma2(zzB[12], w6.x, a0); a1 = fma2(zzB[13], w6.y, a1);
            a0 = add2(a0, a1);
            float t0, t1;
            upk2(a0, t0, t1);
            float e0 = (t0 > 0.f) ? t0 : (__expf(t0) - 1.f);
            float e1 = (t1 > 0.f) ? t1 : (__expf(t1) - 1.f);
            ull aa0 = pk2(e0, e0), aa1 = pk2(e1, e1);
            h2aB = fma2(aa0, w2a.x, h2aB);
            h2bB = fma2(aa0, w2a.y, h2bB);
            h2aB = fma2(aa1, w2b.x, h2aB);
            h2bB = fma2(aa1, w2b.y, h2bB);
        }
    }
    {
        float4 o4;
        upk2(h2aA, o4.x, o4.y);
        upk2(h2bA, o4.z, o4.w);
        g_h2p[head * NN + n0] = o4;
    }
    if (v1) {
        float4 o4;
        upk2(h2aB, o4.x, o4.y);
        upk2(h2bB, o4.z, o4.w);
        g_h2p[head * NN + n1] = o4;
    }
}

// Layer-2: phase A combines 8 head partials + precomputes a2 scalars
//          | grid barrier | phase B: softmax-aggregate.
__global__ void __launch_bounds__(256)
k_layer2(float* __restrict__ out, const float* __restrict__ b2,
         const float* __restrict__ as2, const float* __restrict__ ad2) {
    const int t = threadIdx.x;
    const int n = blockIdx.x * 256 + t;
    const float s0 = __ldg(as2 + 0), s1 = __ldg(as2 + 1),
                s2 = __ldg(as2 + 2), s3 = __ldg(as2 + 3);
    if (n < NN) {
        float hx = 0.f, hy = 0.f, hz = 0.f, hw = 0.f;
#pragma unroll
        for (int h = 0; h < NH; h++) {
            float4 p = g_h2p[h * NN + n];
            hx += p.x; hy += p.y; hz += p.z; hw += p.w;
        }
        g_h2[n] = make_float4(hx, hy, hz, hw);
        g_a2s[n] = hx * s0 + hy * s1 + hz * s2 + hw * s3;
        g_a2d[n] = hx * __ldg(ad2 + 0) + hy * __ldg(ad2 + 1) +
                   hz * __ldg(ad2 + 2) + hw * __ldg(ad2 + 3);
    }
    grid_bar(&g_td, NB);
    if (n >= NN) return;
    const float adn = g_a2d[n];
    const int r0 = g_rowptr[n], r1 = g_rowptr[n + 1];
    float ss = 0.f, ax = 0.f, ay = 0.f, az = 0.f, aw = 0.f;
    for (int e = r0; e < r1; e++) {
        int s = g_col[e];
        float v = lrelu(g_a2s[s] + adn);
        float w = __expf(v);
        ss += w;
        float4 hv = g_h2[s];
        ax = fmaf(w, hv.x, ax);
        ay = fmaf(w, hv.y, ay);
        az = fmaf(w, hv.z, az);
        aw = fmaf(w, hv.w, aw);
    }
    float inv = 1.f / (ss + 1e-16f);
    float4 o4;
    o4.x = ax * inv + __ldg(b2 + 0);
    o4.y = ay * inv + __ldg(b2 + 1);
    o4.z = az * inv + __ldg(b2 + 2);
    o4.w = aw * inv + __ldg(b2 + 3);
    ((float4*)out)[n] = o4;
}

extern "C" void kernel_launch(void* const* d_in, const int* in_sizes, int n_in,
                              void* d_out, int out_size) {
    const float* x   = (const float*)d_in[0];
    const void*  ei  = d_in[1];
    const float* W1  = (const float*)d_in[2];
    const float* as1 = (const float*)d_in[3];
    const float* ad1 = (const float*)d_in[4];
    const float* b1  = (const float*)d_in[5];
    const float* W2  = (const float*)d_in[6];
    const float* as2 = (const float*)d_in[7];
    const float* ad2 = (const float*)d_in[8];
    const float* b2  = (const float*)d_in[9];
    float* out = (float*)d_out;

    k_histF<<<HB, 256>>>(ei, W1, as1, ad1);
    k_build<<<NB, 256>>>(x, ei);
    k_agg<<<(NN + 127) / 128, 128>>>();
    dim3 pg(NB, NH);
    k_proj<<<pg, 128>>>(W1, b1, W2);
    k_layer2<<<NB, 256>>>(out, b2, as2, ad2);
}